// round 17
// baseline (speedup 1.0000x reference)
#include <cuda_runtime.h>
#include <math.h>

#define BB 512
#define CC 256
#define NW 8                 // 256 concepts / 32 bits
#define TEMP_INV (1.0f/0.07f)
#define GRID 512
#define NGRP 32              // completion-tree first level (16 blocks/group)

// ---- persistent scratch (no allocation allowed) ----
__device__ float    g_clip[2*BB];    // per-row (lse - diag): img [0..511], txt [512..1023]
__device__ float    g_ccl [2*BB];    // per-row bce sum [0..511], mask sum [512..1023]
__device__ float    g_lsec[BB];      // per-row log-sum-exp of cis (unshifted)
__device__ float    g_kl  [BB];      // per-row KL term
__device__ unsigned g_bits[BB*NW];   // binary concept bitmasks (row-major [row][word])
__device__ unsigned g_doneA[NGRP];   // first-level completion counters (wrap -> replay-safe)
__device__ unsigned g_doneB = 0;     // second-level counter

// ---------- deterministic block reductions (256 threads) ----------
// RULE: each helper's static smem buffer is used at most ONCE per kernel.

__device__ __forceinline__ void blockMax2(float& a, float& b) {
    __shared__ float sh[2][8];
    int tid = threadIdx.x;
    #pragma unroll
    for (int o = 16; o > 0; o >>= 1) {
        a = fmaxf(a, __shfl_down_sync(0xffffffffu, a, o));
        b = fmaxf(b, __shfl_down_sync(0xffffffffu, b, o));
    }
    if ((tid & 31) == 0) { int w = tid >> 5; sh[0][w] = a; sh[1][w] = b; }
    __syncthreads();
    float ra = sh[0][0], rb = sh[1][0];
    #pragma unroll
    for (int w = 1; w < 8; w++) { ra = fmaxf(ra, sh[0][w]); rb = fmaxf(rb, sh[1][w]); }
    a = ra; b = rb;
}

__device__ __forceinline__ void blockSum5(float& a, float& b, float& c, float& d, float& e) {
    __shared__ float sh[5][8];
    int tid = threadIdx.x;
    #pragma unroll
    for (int o = 16; o > 0; o >>= 1) {
        a += __shfl_down_sync(0xffffffffu, a, o);
        b += __shfl_down_sync(0xffffffffu, b, o);
        c += __shfl_down_sync(0xffffffffu, c, o);
        d += __shfl_down_sync(0xffffffffu, d, o);
        e += __shfl_down_sync(0xffffffffu, e, o);
    }
    if ((tid & 31) == 0) {
        int w = tid >> 5;
        sh[0][w] = a; sh[1][w] = b; sh[2][w] = c; sh[3][w] = d; sh[4][w] = e;
    }
    __syncthreads();
    float ra = 0.f, rb = 0.f, rc = 0.f, rd = 0.f, re = 0.f;
    #pragma unroll
    for (int w = 0; w < 8; w++) {
        ra += sh[0][w]; rb += sh[1][w]; rc += sh[2][w]; rd += sh[3][w]; re += sh[4][w];
    }
    a = ra; b = rb; c = rc; d = rd; e = re;
}

__device__ __forceinline__ void blockSum2(float& a, float& b) {
    __shared__ float sh[2][8];
    int tid = threadIdx.x;
    #pragma unroll
    for (int o = 16; o > 0; o >>= 1) {
        a += __shfl_down_sync(0xffffffffu, a, o);
        b += __shfl_down_sync(0xffffffffu, b, o);
    }
    if ((tid & 31) == 0) { int w = tid >> 5; sh[0][w] = a; sh[1][w] = b; }
    __syncthreads();
    float ra = 0.f, rb = 0.f;
    #pragma unroll
    for (int w = 0; w < 8; w++) { ra += sh[0][w]; rb += sh[1][w]; }
    a = ra; b = rb;
}

__device__ __forceinline__ void blockSum4b(float& a, float& b, float& c, float& d) {
    __shared__ float sh[4][8];
    int tid = threadIdx.x;
    #pragma unroll
    for (int o = 16; o > 0; o >>= 1) {
        a += __shfl_down_sync(0xffffffffu, a, o);
        b += __shfl_down_sync(0xffffffffu, b, o);
        c += __shfl_down_sync(0xffffffffu, c, o);
        d += __shfl_down_sync(0xffffffffu, d, o);
    }
    if ((tid & 31) == 0) { int w = tid >> 5; sh[0][w] = a; sh[1][w] = b; sh[2][w] = c; sh[3][w] = d; }
    __syncthreads();
    float ra = 0.f, rb = 0.f, rc = 0.f, rd = 0.f;
    #pragma unroll
    for (int w = 0; w < 8; w++) { ra += sh[0][w]; rb += sh[1][w]; rc += sh[2][w]; rd += sh[3][w]; }
    a = ra; b = rb; c = rc; d = rd;
}

// =======================================================================
// K1: per-row BCE + bitmasks + CLIP lse + cis lse.
// ONE blockMax2 + ONE blockSum5 -> no smem-buffer reuse.
// =======================================================================
__global__ void __launch_bounds__(256, 4)
k1_rows(const float* __restrict__ img,
        const float* __restrict__ txt,
        const float* __restrict__ cl,
        const int*   __restrict__ mc,
        const float* __restrict__ cis) {
    const int b   = blockIdx.x;
    const int tid = threadIdx.x;

    // issue all global loads up front
    int   m  = mc[(size_t)b * CC + tid];
    float x  = cl[(size_t)b * CC + tid];
    const float* ri = img + (size_t)b * BB;
    const float* rt = txt + (size_t)b * BB;
    float i0 = ri[tid], i1 = ri[tid + 256];
    float t0 = rt[tid], t1 = rt[tid + 256];
    float c0 = cis[(size_t)b * BB + tid];
    float c1 = cis[(size_t)b * BB + tid + 256];

    float mask = (m != -1) ? 1.f : 0.f;
    float tgt  = (m > 0)   ? 1.f : 0.f;
    float la   = (x > 0.f) ? (x + log1pf(__expf(-x))) : log1pf(__expf(x));
    float loss = (la - x * tgt) * mask;
    unsigned ball = __ballot_sync(0xffffffffu, m > 0);
    if ((tid & 31) == 0) g_bits[b * NW + (tid >> 5)] = ball;

    float mi = fmaxf(i0, i1), mt = fmaxf(t0, t1);
    blockMax2(mi, mt);
    float si = __expf(i0 - mi) + __expf(i1 - mi);
    float st = __expf(t0 - mt) + __expf(t1 - mt);
    float ec = __expf(c0) + __expf(c1);      // unshifted: cis ~ N(0,1), safe in fp32
    float ls = loss, ms = mask;
    blockSum5(si, st, ls, ms, ec);
    if (tid == 0) {
        g_clip[b]      = mi + logf(si) - ri[b];
        g_clip[BB + b] = mt + logf(st) - rt[b];
        g_ccl[b]       = ls;
        g_ccl[BB + b]  = ms;
        g_lsec[b]      = logf(ec);
    }
}

// =======================================================================
// K2: Jaccard -> KL per row (512 blocks, register-only; no maxc, no ec)
// =======================================================================
__global__ void __launch_bounds__(256, 4)
k2_kl(const float* __restrict__ cis, float* __restrict__ out) {
    const int b   = blockIdx.x;
    const int tid = threadIdx.x;
    const uint4* bits4 = (const uint4*)g_bits;   // 2 uint4 per row

    // own row's mask (broadcast loads); count from registers
    uint4 a0 = bits4[2 * b], a1 = bits4[2 * b + 1];
    int cnti = __popc(a0.x) + __popc(a0.y) + __popc(a0.z) + __popc(a0.w)
             + __popc(a1.x) + __popc(a1.y) + __popc(a1.z) + __popc(a1.w);

    // cis values (L2-warm from k1)
    float c0 = cis[(size_t)b * BB + tid];
    float c1 = cis[(size_t)b * BB + tid + 256];

    // this thread's two j bit-rows (issue early)
    uint4 p0 = bits4[2 * tid],         p1 = bits4[2 * tid + 1];
    uint4 q0 = bits4[2 * (tid + 256)], q1 = bits4[2 * (tid + 256) + 1];

    float maxs = (cnti > 0) ? TEMP_INV : 0.f;   // sim(i,i)=1 when row nonempty

    float es = 0.f, num = 0.f;
    {
        int inter = __popc(a0.x & p0.x) + __popc(a0.y & p0.y)
                  + __popc(a0.z & p0.z) + __popc(a0.w & p0.w)
                  + __popc(a1.x & p1.x) + __popc(a1.y & p1.y)
                  + __popc(a1.z & p1.z) + __popc(a1.w & p1.w);
        int uni   = __popc(a0.x | p0.x) + __popc(a0.y | p0.y)
                  + __popc(a0.z | p0.z) + __popc(a0.w | p0.w)
                  + __popc(a1.x | p1.x) + __popc(a1.y | p1.y)
                  + __popc(a1.z | p1.z) + __popc(a1.w | p1.w);
        float sim = (uni > 0) ? (float)inter / (float)uni : 0.f;
        float s   = sim * TEMP_INV;
        float e   = __expf(s - maxs);
        es  += e;
        num += e * (s - c0);
    }
    {
        int inter = __popc(a0.x & q0.x) + __popc(a0.y & q0.y)
                  + __popc(a0.z & q0.z) + __popc(a0.w & q0.w)
                  + __popc(a1.x & q1.x) + __popc(a1.y & q1.y)
                  + __popc(a1.z & q1.z) + __popc(a1.w & q1.w);
        int uni   = __popc(a0.x | q0.x) + __popc(a0.y | q0.y)
                  + __popc(a0.z | q0.z) + __popc(a0.w | q0.w)
                  + __popc(a1.x | q1.x) + __popc(a1.y | q1.y)
                  + __popc(a1.z | q1.z) + __popc(a1.w | q1.w);
        float sim = (uni > 0) ? (float)inter / (float)uni : 0.f;
        float s   = sim * TEMP_INV;
        float e   = __expf(s - maxs);
        es  += e;
        num += e * (s - c1);
    }
    blockSum2(es, num);
    if (tid == 0)
        g_kl[b] = num / es - maxs - logf(es) + g_lsec[b];

    // -------- two-level completion tree; last block folds -> out --------
    __shared__ bool is_last;
    __syncthreads();
    if (tid == 0) {
        __threadfence();
        unsigned t = atomicInc(&g_doneA[b >> 4], 15u);   // wraps -> replay-safe
        is_last = false;
        if (t == 15u) {
            unsigned u = atomicInc(&g_doneB, NGRP - 1);
            is_last = (u == NGRP - 1);
        }
    }
    __syncthreads();
    if (is_last) {
        __threadfence();   // acquire other blocks' writes
        float cs = 0.f, ls = 0.f, ms = 0.f, ks = 0.f;
        #pragma unroll
        for (int k = 0; k < 4; k++) cs += __ldcg(&g_clip[tid + k * 256]);
        #pragma unroll
        for (int k = 0; k < 2; k++) {
            ls += __ldcg(&g_ccl[tid + k * 256]);
            ms += __ldcg(&g_ccl[BB + tid + k * 256]);
            ks += __ldcg(&g_kl[tid + k * 256]);
        }
        blockSum4b(cs, ls, ms, ks);
        if (tid == 0) {
            float clip_loss = cs / (2.f * BB);
            float bce_loss  = ls / (ms + 1e-8f);
            float kl_loss   = ks / (float)BB;
            out[0] = clip_loss + 0.5f * bce_loss + 0.3f * kl_loss;
        }
    }
}

extern "C" void kernel_launch(void* const* d_in, const int* in_sizes, int n_in,
                              void* d_out, int out_size) {
    const float* img = (const float*)d_in[0];   // logits_per_image [512,512]
    const float* txt = (const float*)d_in[1];   // logits_per_text  [512,512]
    const float* cl  = (const float*)d_in[2];   // concepts_logits  [512,256]
    const float* cis = (const float*)d_in[3];   // concepts_image_similarity [512,512]
    const int*   mc  = (const int*)d_in[4];     // medical_concepts [512,256]
    float* out = (float*)d_out;

    k1_rows<<<GRID, 256>>>(img, txt, cl, mc, cis);
    k2_kl  <<<GRID, 256>>>(cis, out);
}